// round 15
// baseline (speedup 1.0000x reference)
#include <cuda_runtime.h>
#include <math.h>

#define TS  2048
#define BB  32
#define ISZ 256
#define HS  512
#define G4  2048
#define KS  64
#define VS  64
#define NP  194
#define NLB 128   // persistent LSTM blocks (<= SM count, one wave guaranteed)

// ---------------- scratch (static device memory; no allocations) ----------------
__device__ __align__(16) float g_xproj[(size_t)TS * G4 * BB];   // TRANSPOSED: [t][gate_row][batch]
__device__ float4 g_h4[2 * (HS / 4) * BB];                      // double-buffered h, [buf][j/4][b]
__device__ __align__(16) float g_raw[(size_t)TS * BB * NP];
__device__ __align__(16) float g_ks[(size_t)TS * BB * KS];
__device__ __align__(16) float g_qs[(size_t)TS * BB * KS];
__device__ __align__(16) float g_vs[(size_t)TS * BB * VS];
__device__ float g_bs[(size_t)TS * BB];
__device__ float g_ms[(size_t)TS * BB];
__device__ __align__(16) float g_s[(size_t)TS * BB * VS];
__device__ __align__(16) float g_Wcat[NP * HS];
__device__ float g_bcat[NP];
__device__ float g_blstm[G4];
__device__ unsigned g_bar_count;

__device__ __forceinline__ float sigm(float x)  { return 1.f / (1.f + __expf(-x)); }
__device__ __forceinline__ float elup1(float x) { return x > 0.f ? x + 1.f : __expf(x); }

// packed fp32x2 helpers (sm_100+)
__device__ __forceinline__ unsigned long long ffma2(unsigned long long a, unsigned long long b,
                                                    unsigned long long c) {
    unsigned long long d;
    asm("fma.rn.f32x2 %0, %1, %2, %3;" : "=l"(d) : "l"(a), "l"(b), "l"(c));
    return d;
}
__device__ __forceinline__ unsigned long long pk2(float lo, float hi) {
    unsigned long long r;
    asm("mov.b64 %0, {%1, %2};" : "=l"(r) : "f"(lo), "f"(hi));
    return r;
}
__device__ __forceinline__ void upk2(float& lo, float& hi, unsigned long long v) {
    asm("mov.b64 {%0, %1}, %2;" : "=f"(lo), "=f"(hi) : "l"(v));
}

// ---------------- pack: Wcat/bcat (k|v|q|b|m), fused LSTM bias, barrier reset ----------------
__global__ void pack_kernel(const float* __restrict__ Wk, const float* __restrict__ bk,
                            const float* __restrict__ Wv, const float* __restrict__ bv,
                            const float* __restrict__ Wb, const float* __restrict__ bb,
                            const float* __restrict__ Wq, const float* __restrict__ bq,
                            const float* __restrict__ Wm, const float* __restrict__ bm,
                            const float* __restrict__ b_ih, const float* __restrict__ b_hh)
{
    int idx = blockIdx.x * 256 + threadIdx.x;
    if (idx == 0) g_bar_count = 0;      // reset monotonic grid-barrier counter every launch/replay
    if (idx < NP * HS) {
        int row = idx / HS, col = idx % HS;
        float v;
        if      (row < 64)  v = Wk[row * HS + col];
        else if (row < 128) v = Wv[(row - 64) * HS + col];
        else if (row < 192) v = Wq[(row - 128) * HS + col];
        else if (row == 192) v = Wb[col];
        else                 v = Wm[col];
        g_Wcat[idx] = v;
    } else if (idx < NP * HS + NP) {
        int row = idx - NP * HS;
        float v;
        if      (row < 64)  v = bk[row];
        else if (row < 128) v = bv[row - 64];
        else if (row < 192) v = bq[row - 128];
        else if (row == 192) v = bb[0];
        else                 v = bm[0];
        g_bcat[row] = v;
    } else if (idx < NP * HS + NP + G4) {
        int r = idx - NP * HS - NP;
        g_blstm[r] = b_ih[r] + b_hh[r];
    }
}

// ---------------- SGEMM: C[M,N] = A[M,K] @ B[N,K]^T + bias[N] ----------------
// 128x128 tile, 256 threads, 8x8 per thread via FFMA2, double-buffered smem.
// M multiple of 128, K multiple of 16, N arbitrary (guarded).
__global__ void __launch_bounds__(256)
sgemm_bias(const float* __restrict__ A, int lda,
           const float* __restrict__ B, int ldb,
           const float* __restrict__ bias,
           float* __restrict__ C, int ldc,
           int N, int K)
{
    __shared__ __align__(16) float As[2][16][132];
    __shared__ __align__(16) float Bs[2][16][132];
    const int tid = threadIdx.x;
    const int m0 = blockIdx.y * 128, n0 = blockIdx.x * 128;
    const int lrow = tid >> 1;
    const int lcol = (tid & 1) * 8;
    const int tx = tid & 15, ty = tid >> 4;
    const int tn0 = tx * 8, tm0 = ty * 8;

    unsigned long long acc2[4][8];
#pragma unroll
    for (int i = 0; i < 4; i++)
#pragma unroll
        for (int j = 0; j < 8; j++) acc2[i][j] = 0ull;

    const float* Arow = A + (size_t)(m0 + lrow) * lda;
    const bool  bok   = (n0 + lrow) < N;
    const float* Brow = B + (size_t)(bok ? (n0 + lrow) : 0) * ldb;

    float4 a0, a1, b0, b1;
    a0 = *reinterpret_cast<const float4*>(Arow + lcol);
    a1 = *reinterpret_cast<const float4*>(Arow + lcol + 4);
    b0 = b1 = make_float4(0.f, 0.f, 0.f, 0.f);
    if (bok) {
        b0 = *reinterpret_cast<const float4*>(Brow + lcol);
        b1 = *reinterpret_cast<const float4*>(Brow + lcol + 4);
    }
    int buf = 0;
    {
        As[0][lcol + 0][lrow] = a0.x; As[0][lcol + 1][lrow] = a0.y;
        As[0][lcol + 2][lrow] = a0.z; As[0][lcol + 3][lrow] = a0.w;
        As[0][lcol + 4][lrow] = a1.x; As[0][lcol + 5][lrow] = a1.y;
        As[0][lcol + 6][lrow] = a1.z; As[0][lcol + 7][lrow] = a1.w;
        Bs[0][lcol + 0][lrow] = b0.x; Bs[0][lcol + 1][lrow] = b0.y;
        Bs[0][lcol + 2][lrow] = b0.z; Bs[0][lcol + 3][lrow] = b0.w;
        Bs[0][lcol + 4][lrow] = b1.x; Bs[0][lcol + 5][lrow] = b1.y;
        Bs[0][lcol + 6][lrow] = b1.z; Bs[0][lcol + 7][lrow] = b1.w;
    }
    __syncthreads();

    for (int k0 = 0; k0 < K; k0 += 16) {
        const bool more = (k0 + 16) < K;
        if (more) {
            a0 = *reinterpret_cast<const float4*>(Arow + k0 + 16 + lcol);
            a1 = *reinterpret_cast<const float4*>(Arow + k0 + 16 + lcol + 4);
            if (bok) {
                b0 = *reinterpret_cast<const float4*>(Brow + k0 + 16 + lcol);
                b1 = *reinterpret_cast<const float4*>(Brow + k0 + 16 + lcol + 4);
            }
        }
#pragma unroll
        for (int k = 0; k < 16; k++) {
            const ulonglong2* Ap = reinterpret_cast<const ulonglong2*>(&As[buf][k][tm0]);
            ulonglong2 A01 = Ap[0], A23 = Ap[1];
            float4 bl = *reinterpret_cast<const float4*>(&Bs[buf][k][tn0]);
            float4 bh = *reinterpret_cast<const float4*>(&Bs[buf][k][tn0 + 4]);
            unsigned long long ap[4] = {A01.x, A01.y, A23.x, A23.y};
            unsigned long long bd[8] = {pk2(bl.x, bl.x), pk2(bl.y, bl.y),
                                        pk2(bl.z, bl.z), pk2(bl.w, bl.w),
                                        pk2(bh.x, bh.x), pk2(bh.y, bh.y),
                                        pk2(bh.z, bh.z), pk2(bh.w, bh.w)};
#pragma unroll
            for (int i = 0; i < 4; i++)
#pragma unroll
                for (int j = 0; j < 8; j++)
                    acc2[i][j] = ffma2(ap[i], bd[j], acc2[i][j]);
        }
        if (more) {
            int nb = buf ^ 1;
            As[nb][lcol + 0][lrow] = a0.x; As[nb][lcol + 1][lrow] = a0.y;
            As[nb][lcol + 2][lrow] = a0.z; As[nb][lcol + 3][lrow] = a0.w;
            As[nb][lcol + 4][lrow] = a1.x; As[nb][lcol + 5][lrow] = a1.y;
            As[nb][lcol + 6][lrow] = a1.z; As[nb][lcol + 7][lrow] = a1.w;
            Bs[nb][lcol + 0][lrow] = b0.x; Bs[nb][lcol + 1][lrow] = b0.y;
            Bs[nb][lcol + 2][lrow] = b0.z; Bs[nb][lcol + 3][lrow] = b0.w;
            Bs[nb][lcol + 4][lrow] = b1.x; Bs[nb][lcol + 5][lrow] = b1.y;
            Bs[nb][lcol + 6][lrow] = b1.z; Bs[nb][lcol + 7][lrow] = b1.w;
            __syncthreads();
            buf = nb;
        }
    }

    const bool vec = ((ldc & 3) == 0) && (n0 + tn0 + 7) < N;
#pragma unroll
    for (int i = 0; i < 4; i++) {
        float lo[8], hi[8];
#pragma unroll
        for (int j = 0; j < 8; j++) upk2(lo[j], hi[j], acc2[i][j]);
        size_t r0 = (size_t)(m0 + tm0 + 2 * i) * ldc + n0 + tn0;
        size_t r1 = r0 + ldc;
        if (vec) {
            float4 bl = *reinterpret_cast<const float4*>(bias + n0 + tn0);
            float4 bh = *reinterpret_cast<const float4*>(bias + n0 + tn0 + 4);
            *reinterpret_cast<float4*>(C + r0)     = make_float4(lo[0] + bl.x, lo[1] + bl.y, lo[2] + bl.z, lo[3] + bl.w);
            *reinterpret_cast<float4*>(C + r0 + 4) = make_float4(lo[4] + bh.x, lo[5] + bh.y, lo[6] + bh.z, lo[7] + bh.w);
            *reinterpret_cast<float4*>(C + r1)     = make_float4(hi[0] + bl.x, hi[1] + bl.y, hi[2] + bl.z, hi[3] + bl.w);
            *reinterpret_cast<float4*>(C + r1 + 4) = make_float4(hi[4] + bh.x, hi[5] + bh.y, hi[6] + bh.z, hi[7] + bh.w);
        } else {
#pragma unroll
            for (int j = 0; j < 8; j++) {
                int n = n0 + tn0 + j;
                if (n < N) {
                    float bv_ = bias[n];
                    C[r0 + j] = lo[j] + bv_;
                    C[r1 + j] = hi[j] + bv_;
                }
            }
        }
    }
}

// ---------------- xproj-transposed SGEMM ----------------
// C_T[(n>>5)*G4*32 + m*32 + (n&31)] = sum_k A[m,k]*B[n,k] + bias[m]
// A = W_ih [G4, ISZ], B = inputs [T*B, ISZ], m = gate row, n = t*32+b.
// M = G4 (grid.y = 16), N = T*B (grid.x = 512), both multiples of 128 -> no guards.
__global__ void __launch_bounds__(256)
sgemm_bias_xT(const float* __restrict__ A, const float* __restrict__ B,
              const float* __restrict__ bias, float* __restrict__ C, int K)
{
    __shared__ __align__(16) float As[2][16][132];
    __shared__ __align__(16) float Bs[2][16][132];
    const int tid = threadIdx.x;
    const int m0 = blockIdx.y * 128, n0 = blockIdx.x * 128;
    const int lrow = tid >> 1;
    const int lcol = (tid & 1) * 8;
    const int tx = tid & 15, ty = tid >> 4;
    const int tn0 = tx * 8, tm0 = ty * 8;

    unsigned long long acc2[4][8];
#pragma unroll
    for (int i = 0; i < 4; i++)
#pragma unroll
        for (int j = 0; j < 8; j++) acc2[i][j] = 0ull;

    const float* Arow = A + (size_t)(m0 + lrow) * ISZ;
    const float* Brow = B + (size_t)(n0 + lrow) * ISZ;

    float4 a0, a1, b0, b1;
    a0 = *reinterpret_cast<const float4*>(Arow + lcol);
    a1 = *reinterpret_cast<const float4*>(Arow + lcol + 4);
    b0 = *reinterpret_cast<const float4*>(Brow + lcol);
    b1 = *reinterpret_cast<const float4*>(Brow + lcol + 4);
    int buf = 0;
    {
        As[0][lcol + 0][lrow] = a0.x; As[0][lcol + 1][lrow] = a0.y;
        As[0][lcol + 2][lrow] = a0.z; As[0][lcol + 3][lrow] = a0.w;
        As[0][lcol + 4][lrow] = a1.x; As[0][lcol + 5][lrow] = a1.y;
        As[0][lcol + 6][lrow] = a1.z; As[0][lcol + 7][lrow] = a1.w;
        Bs[0][lcol + 0][lrow] = b0.x; Bs[0][lcol + 1][lrow] = b0.y;
        Bs[0][lcol + 2][lrow] = b0.z; Bs[0][lcol + 3][lrow] = b0.w;
        Bs[0][lcol + 4][lrow] = b1.x; Bs[0][lcol + 5][lrow] = b1.y;
        Bs[0][lcol + 6][lrow] = b1.z; Bs[0][lcol + 7][lrow] = b1.w;
    }
    __syncthreads();

    for (int k0 = 0; k0 < K; k0 += 16) {
        const bool more = (k0 + 16) < K;
        if (more) {
            a0 = *reinterpret_cast<const float4*>(Arow + k0 + 16 + lcol);
            a1 = *reinterpret_cast<const float4*>(Arow + k0 + 16 + lcol + 4);
            b0 = *reinterpret_cast<const float4*>(Brow + k0 + 16 + lcol);
            b1 = *reinterpret_cast<const float4*>(Brow + k0 + 16 + lcol + 4);
        }
#pragma unroll
        for (int k = 0; k < 16; k++) {
            const ulonglong2* Ap = reinterpret_cast<const ulonglong2*>(&As[buf][k][tm0]);
            ulonglong2 A01 = Ap[0], A23 = Ap[1];
            float4 bl = *reinterpret_cast<const float4*>(&Bs[buf][k][tn0]);
            float4 bh = *reinterpret_cast<const float4*>(&Bs[buf][k][tn0 + 4]);
            unsigned long long ap[4] = {A01.x, A01.y, A23.x, A23.y};
            unsigned long long bd[8] = {pk2(bl.x, bl.x), pk2(bl.y, bl.y),
                                        pk2(bl.z, bl.z), pk2(bl.w, bl.w),
                                        pk2(bh.x, bh.x), pk2(bh.y, bh.y),
                                        pk2(bh.z, bh.z), pk2(bh.w, bh.w)};
#pragma unroll
            for (int i = 0; i < 4; i++)
#pragma unroll
                for (int j = 0; j < 8; j++)
                    acc2[i][j] = ffma2(ap[i], bd[j], acc2[i][j]);
        }
        if (more) {
            int nb = buf ^ 1;
            As[nb][lcol + 0][lrow] = a0.x; As[nb][lcol + 1][lrow] = a0.y;
            As[nb][lcol + 2][lrow] = a0.z; As[nb][lcol + 3][lrow] = a0.w;
            As[nb][lcol + 4][lrow] = a1.x; As[nb][lcol + 5][lrow] = a1.y;
            As[nb][lcol + 6][lrow] = a1.z; As[nb][lcol + 7][lrow] = a1.w;
            Bs[nb][lcol + 0][lrow] = b0.x; Bs[nb][lcol + 1][lrow] = b0.y;
            Bs[nb][lcol + 2][lrow] = b0.z; Bs[nb][lcol + 3][lrow] = b0.w;
            Bs[nb][lcol + 4][lrow] = b1.x; Bs[nb][lcol + 5][lrow] = b1.y;
            Bs[nb][lcol + 6][lrow] = b1.z; Bs[nb][lcol + 7][lrow] = b1.w;
            __syncthreads();
            buf = nb;
        }
    }

    // epilogue: n-group constant per thread (tn0 % 32 in {0,8,16,24}, j<8 stays inside)
    const int nb_ = n0 + tn0;
    const size_t grp = (size_t)(nb_ >> 5) * G4 * 32 + (nb_ & 31);
#pragma unroll
    for (int i = 0; i < 4; i++) {
        float lo[8], hi[8];
#pragma unroll
        for (int j = 0; j < 8; j++) upk2(lo[j], hi[j], acc2[i][j]);
        int mlo = m0 + tm0 + 2 * i, mhi = mlo + 1;
        float blo = bias[mlo], bhi = bias[mhi];
        float* plo = C + grp + (size_t)mlo * 32;
        float* phi = C + grp + (size_t)mhi * 32;
        *reinterpret_cast<float4*>(plo)     = make_float4(lo[0] + blo, lo[1] + blo, lo[2] + blo, lo[3] + blo);
        *reinterpret_cast<float4*>(plo + 4) = make_float4(lo[4] + blo, lo[5] + blo, lo[6] + blo, lo[7] + blo);
        *reinterpret_cast<float4*>(phi)     = make_float4(hi[0] + bhi, hi[1] + bhi, hi[2] + bhi, hi[3] + bhi);
        *reinterpret_cast<float4*>(phi + 4) = make_float4(hi[4] + bhi, hi[5] + bhi, hi[6] + bhi, hi[7] + bhi);
    }
}

// ---------------- persistent LSTM scan (512 thr/block, FFMA2) ----------------
__device__ __forceinline__ void grid_barrier(unsigned target)
{
    __syncthreads();
    if (threadIdx.x == 0) {
        unsigned* p = &g_bar_count;
        asm volatile("red.release.gpu.global.add.u32 [%0], 1;" :: "l"(p) : "memory");
        unsigned v;
        do {
            asm volatile("ld.acquire.gpu.global.u32 %0, [%1];" : "=r"(v) : "l"(p) : "memory");
        } while ((int)(v - target) < 0);
    }
    __syncthreads();
}

// dynamic smem layout (bytes):
//   [0, 32768)           float4 Wq[256][8]
//   [32768, 65536)       u64 red2[16][8][32]
//   [65536, 67584)       float gates[16][32]
//   [67584, 68096)       float c_s[4][32]
#define LSMEM_BYTES 68096

__global__ void __launch_bounds__(512)
lstm_kernel(const float* __restrict__ h0, const float* __restrict__ c0,
            const float* __restrict__ W_hh, float* __restrict__ out)
{
    extern __shared__ __align__(16) char smem[];
    float4*              Wq     = reinterpret_cast<float4*>(smem);
    unsigned long long*  red2   = reinterpret_cast<unsigned long long*>(smem + 32768);
    float*               redf   = reinterpret_cast<float*>(smem + 32768);
    float*               gates  = reinterpret_cast<float*>(smem + 65536);
    float*               c_s    = reinterpret_cast<float*>(smem + 67584);

    const int bid = blockIdx.x, tid = threadIdx.x;
    const int w = tid >> 5, lane = tid & 31;

    // stage W_hh pairs: Wq[jh][rp]
    for (int idx = tid; idx < 256 * 8; idx += 512) {
        int jh = idx >> 3, rp = idx & 7;
        int r0 = 2 * rp, r1 = 2 * rp + 1;
        size_t g0 = (size_t)((r0 >> 2) * HS + bid * 4 + (r0 & 3)) * HS;
        size_t g1 = (size_t)((r1 >> 2) * HS + bid * 4 + (r1 & 3)) * HS;
        int j0 = 2 * jh, j1 = 2 * jh + 1;
        Wq[idx] = make_float4(W_hh[g0 + j0], W_hh[g1 + j0], W_hh[g0 + j1], W_hh[g1 + j1]);
    }
    if (tid < 128) {
        int c = tid & 3, b = tid >> 2;
        int jcol = bid * 4 + c;
        c_s[c * 32 + b] = c0[b * HS + jcol];
        ((float*)g_h4)[(bid * BB + b) * 4 + c] = h0[b * HS + jcol];  // buffer 0
    }

    const int r = tid >> 5, bb_ = tid & 31;
    const int rp_r = r >> 1, e_r = r & 1;
    const size_t growR = (size_t)((r >> 2) * HS + bid * 4 + (r & 3));
    const int cc = tid & 3, ba = tid >> 2;
    const int jcol = bid * 4 + cc;

    // coalesced x_proj stream: [t][gate_row][batch], warp reads one 128B line
    const float* xpp = g_xproj + growR * 32 + bb_;
    float xp = xpp[0];

    unsigned barn = 1;
    grid_barrier(barn * NLB);

    for (int t = 0; t < TS; t++) {
        const float4* hbuf = g_h4 + (size_t)(t & 1) * (HS / 4) * BB;
        float*        hout = (float*)(g_h4 + (size_t)((t + 1) & 1) * (HS / 4) * BB);

        // prefetch next step's x_proj line (independent of h) — hidden under FMA2 phase
        float xp_n = 0.f;
        if (t + 1 < TS) xp_n = xpp[(size_t)(t + 1) * G4 * 32];

        unsigned long long acc2[8];
#pragma unroll
        for (int rp = 0; rp < 8; rp++) acc2[rp] = 0ull;

#pragma unroll
        for (int jq = 0; jq < 8; jq++) {
            float4 hv = hbuf[(w * 8 + jq) * BB + lane];
            unsigned long long p0 = pk2(hv.x, hv.x);
            unsigned long long p1 = pk2(hv.y, hv.y);
            unsigned long long p2 = pk2(hv.z, hv.z);
            unsigned long long p3 = pk2(hv.w, hv.w);
            const ulonglong2* Wv = reinterpret_cast<const ulonglong2*>(Wq + ((w * 16 + jq * 2) * 8));
#pragma unroll
            for (int rp = 0; rp < 8; rp++) {
                ulonglong2 w0 = Wv[rp];
                ulonglong2 w1 = Wv[8 + rp];
                acc2[rp] = ffma2(p0, w0.x, acc2[rp]);
                acc2[rp] = ffma2(p1, w0.y, acc2[rp]);
                acc2[rp] = ffma2(p2, w1.x, acc2[rp]);
                acc2[rp] = ffma2(p3, w1.y, acc2[rp]);
            }
        }
#pragma unroll
        for (int rp = 0; rp < 8; rp++)
            red2[(w * 8 + rp) * 32 + lane] = acc2[rp];
        __syncthreads();

        {
            float s = xp;
#pragma unroll
            for (int ww = 0; ww < 16; ww++)
                s += redf[((ww * 8 + rp_r) * 32 + bb_) * 2 + e_r];
            gates[r * 32 + bb_] = s;
        }
        __syncthreads();

        if (tid < 128) {
            float gi = gates[(0 + cc) * 32 + ba];
            float gf = gates[(4 + cc) * 32 + ba];
            float gg = gates[(8 + cc) * 32 + ba];
            float go = gates[(12 + cc) * 32 + ba];
            float cn = sigm(gf) * c_s[cc * 32 + ba] + sigm(gi) * tanhf(gg);
            float hn = sigm(go) * tanhf(cn);
            c_s[cc * 32 + ba] = cn;
            hout[(bid * BB + ba) * 4 + cc] = hn;
            out[((size_t)t * BB + ba) * (2 * HS) + jcol] = hn;
        }
        xp = xp_n;
        ++barn;
        grid_barrier(barn * NLB);
    }
}

// ---------------- elu/normalize/sigmoid over packed projections ----------------
__global__ void __launch_bounds__(256) postproc_kernel()
{
    const int w = threadIdx.x >> 5, lane = threadIdx.x & 31;
    const int tb = blockIdx.x * 8 + w;
    const float* rp = g_raw + (size_t)tb * NP;

    float a0 = elup1(rp[lane]), a1 = elup1(rp[32 + lane]);
    float s = a0 + a1;
#pragma unroll
    for (int off = 16; off > 0; off >>= 1) s += __shfl_xor_sync(0xffffffffu, s, off);
    float inv = 1.f / s;
    g_ks[(size_t)tb * KS + lane]      = a0 * inv;
    g_ks[(size_t)tb * KS + 32 + lane] = a1 * inv;

    g_vs[(size_t)tb * VS + lane]      = rp[64 + lane];
    g_vs[(size_t)tb * VS + 32 + lane] = rp[96 + lane];

    float q0 = elup1(rp[128 + lane]), q1 = elup1(rp[160 + lane]);
    float sq = q0 + q1;
#pragma unroll
    for (int off = 16; off > 0; off >>= 1) sq += __shfl_xor_sync(0xffffffffu, sq, off);
    float invq = 1.f / sq;
    g_qs[(size_t)tb * KS + lane]      = q0 * invq;
    g_qs[(size_t)tb * KS + 32 + lane] = q1 * invq;

    if (lane == 0) {
        g_bs[tb] = sigm(rp[192]);
        g_ms[tb] = sigm(rp[193]);
    }
}

// ---------------- delta-rule scan: 64 blocks (b x v-half), 128 thr, 4-way k-split ----------------
__global__ void __launch_bounds__(128) fwm_kernel(const float* __restrict__ F0)
{
    const int b  = blockIdx.x >> 1;
    const int vh = (blockIdx.x & 1) * 32;
    const int tid = threadIdx.x;
    const int vl = tid >> 2;
    const int kq = tid & 3, kb = kq * 16;
    const int v = vh + vl;

    float F[16];
#pragma unroll
    for (int k = 0; k < 16; k++) F[k] = F0[((size_t)b * VS + v) * KS + kb + k];

    __shared__ float k_s[64], q_s[64];

    const float* srcp = (tid < 64) ? (g_ks + tid) : (g_qs + (tid - 64));
    float* dstp = (tid < 64) ? (k_s + tid) : (q_s + (tid - 64));

    size_t base0 = (size_t)b * KS;
    float ld1 = srcp[base0];
    float pv  = g_vs[base0 + v];
    float pb  = g_bs[b];
    float pm  = g_ms[b];

    for (int t = 0; t < TS; t++) {
        *dstp = ld1;
        float vt = pv, bc = pb, mc = pm;
        __syncthreads();

        if (t + 1 < TS) {
            size_t base1 = ((size_t)(t + 1) * BB + b) * KS;
            ld1 = srcp[base1];
            pv  = g_vs[base1 + v];
            pb  = g_bs[(t + 1) * BB + b];
            pm  = g_ms[(t + 1) * BB + b];
        }

        float d0 = 0.f, d1 = 0.f, d2 = 0.f, d3 = 0.f;
#pragma unroll
        for (int k = 0; k < 16; k += 4) {
            d0 = fmaf(F[k],     k_s[kb + k],     d0);
            d1 = fmaf(F[k + 1], k_s[kb + k + 1], d1);
            d2 = fmaf(F[k + 2], k_s[kb + k + 2], d2);
            d3 = fmaf(F[k + 3], k_s[kb + k + 3], d3);
        }
        float d = (d0 + d1) + (d2 + d3);
        d += __shfl_xor_sync(0xffffffffu, d, 1);
        d += __shfl_xor_sync(0xffffffffu, d, 2);
        float nv = bc * (vt - d);

        float o0 = 0.f, o1 = 0.f, o2 = 0.f, o3 = 0.f;
#pragma unroll
        for (int k = 0; k < 16; k += 4) {
            F[k]     = fmaf(nv, k_s[kb + k],     F[k]);     o0 = fmaf(F[k],     q_s[kb + k],     o0);
            F[k + 1] = fmaf(nv, k_s[kb + k + 1], F[k + 1]); o1 = fmaf(F[k + 1], q_s[kb + k + 1], o1);
            F[k + 2] = fmaf(nv, k_s[kb + k + 2], F[k + 2]); o2 = fmaf(F[k + 2], q_s[kb + k + 2], o2);
            F[k + 3] = fmaf(nv, k_s[kb + k + 3], F[k + 3]); o3 = fmaf(F[k + 3], q_s[kb + k + 3], o3);
        }
        float o = (o0 + o1) + (o2 + o3);
        o += __shfl_xor_sync(0xffffffffu, o, 1);
        o += __shfl_xor_sync(0xffffffffu, o, 2);
        if (kq == 0)
            g_s[((size_t)t * BB + b) * VS + v] = o * mc;
        __syncthreads();
    }
}

// ---------------- launch ----------------
extern "C" void kernel_launch(void* const* d_in, const int* in_sizes, int n_in,
                              void* d_out, int out_size)
{
    const float* inputs = (const float*)d_in[0];
    const float* h0     = (const float*)d_in[1];
    const float* c0     = (const float*)d_in[2];
    const float* F0     = (const float*)d_in[3];
    const float* W_ih   = (const float*)d_in[4];
    const float* W_hh   = (const float*)d_in[5];
    const float* b_ih   = (const float*)d_in[6];
    const float* b_hh   = (const float*)d_in[7];
    const float* Wk = (const float*)d_in[8],  *bk = (const float*)d_in[9];
    const float* Wv = (const float*)d_in[10], *bv = (const float*)d_in[11];
    const float* Wb = (const float*)d_in[12], *bb = (const float*)d_in[13];
    const float* Wq = (const float*)d_in[14], *bq = (const float*)d_in[15];
    const float* Wm = (const float*)d_in[16], *bm = (const float*)d_in[17];
    const float* Wlin = (const float*)d_in[18], *blin = (const float*)d_in[19];
    float* out = (float*)d_out;

    float *p_xproj, *p_raw, *p_s, *p_Wcat, *p_bcat, *p_blstm;
    cudaGetSymbolAddress((void**)&p_xproj, g_xproj);
    cudaGetSymbolAddress((void**)&p_raw,   g_raw);
    cudaGetSymbolAddress((void**)&p_s,     g_s);
    cudaGetSymbolAddress((void**)&p_Wcat,  g_Wcat);
    cudaGetSymbolAddress((void**)&p_bcat,  g_bcat);
    cudaGetSymbolAddress((void**)&p_blstm, g_blstm);

    static int smem_set = 0;
    if (!smem_set) {
        cudaFuncSetAttribute(lstm_kernel, cudaFuncAttributeMaxDynamicSharedMemorySize, LSMEM_BYTES);
        smem_set = 1;
    }

    // 1. pack weights/biases (+ barrier counter reset)
    pack_kernel<<<(NP * HS + NP + G4 + 255) / 256, 256>>>(Wk, bk, Wv, bv, Wb, bb, Wq, bq, Wm, bm, b_ih, b_hh);
    // 2. xprojT[t][gate][b] = W_ih @ inputs^T + blstm (transposed store, coalesced LSTM reads)
    sgemm_bias_xT<<<dim3((TS * BB) / 128, G4 / 128), 256>>>(W_ih, inputs, p_blstm, p_xproj, ISZ);
    // 3. sequential LSTM (writes h into out[:, :512] and h double-buffer)
    lstm_kernel<<<NLB, 512, LSMEM_BYTES>>>(h0, c0, W_hh, out);
    // 4. packed FWM projections: raw = h_seq @ Wcat^T + bcat   [65536 x 194]
    sgemm_bias<<<dim3((NP + 127) / 128, (TS * BB) / 128), 256>>>(out, 2 * HS, p_Wcat, HS, p_bcat, p_raw, NP, NP, HS);
    // 5. elu+1 normalize / sigmoid
    postproc_kernel<<<(TS * BB) / 8, 256>>>();
    // 6. sequential fast-weight scan (b x v-half split)
    fwm_kernel<<<2 * BB, 128>>>(F0);
    // 7. out[:, 512:] = s @ Wlin^T + blin
    sgemm_bias<<<dim3(HS / 128, (TS * BB) / 128), 256>>>(p_s, VS, Wlin, VS, blin, out + HS, 2 * HS, HS, VS);
}

// round 16
// speedup vs baseline: 1.0350x; 1.0350x over previous
#include <cuda_runtime.h>
#include <math.h>

#define TS  2048
#define BB  32
#define ISZ 256
#define HS  512
#define G4  2048
#define KS  64
#define VS  64
#define NP  194
#define NLB 128   // persistent LSTM blocks (<= SM count, one wave guaranteed)

// ---------------- scratch (static device memory; no allocations) ----------------
__device__ __align__(16) float g_xproj[(size_t)TS * G4 * BB];   // TRANSPOSED: [t][gate_row][batch]
__device__ float4 g_h4[2 * (HS / 4) * BB];                      // double-buffered h, [buf][j/4][b]
__device__ __align__(16) float g_raw[(size_t)TS * BB * NP];
__device__ __align__(16) float g_ks[(size_t)TS * BB * KS];
__device__ __align__(16) float g_qs[(size_t)TS * BB * KS];
__device__ __align__(16) float g_vs[(size_t)TS * BB * VS];
__device__ float g_bs[(size_t)TS * BB];
__device__ float g_ms[(size_t)TS * BB];
__device__ __align__(16) float g_s[(size_t)TS * BB * VS];
__device__ __align__(16) float g_Wcat[NP * HS];
__device__ float g_bcat[NP];
__device__ float g_blstm[G4];
__device__ unsigned g_bar_count;

__device__ __forceinline__ float elup1(float x) { return x > 0.f ? x + 1.f : __expf(x); }
__device__ __forceinline__ float sigm(float x)  { return 1.f / (1.f + __expf(-x)); }

// fast approx activations (error ~1e-6/1e-7, far under rel_err budget)
__device__ __forceinline__ float rcp_fast(float x) {
    float y; asm("rcp.approx.f32 %0, %1;" : "=f"(y) : "f"(x)); return y;
}
__device__ __forceinline__ float sigm_fast(float x) { return rcp_fast(1.f + __expf(-x)); }
__device__ __forceinline__ float tanh_fast(float x) { return 1.f - 2.f * rcp_fast(1.f + __expf(2.f * x)); }

// packed fp32x2 helpers (sm_100+)
__device__ __forceinline__ unsigned long long ffma2(unsigned long long a, unsigned long long b,
                                                    unsigned long long c) {
    unsigned long long d;
    asm("fma.rn.f32x2 %0, %1, %2, %3;" : "=l"(d) : "l"(a), "l"(b), "l"(c));
    return d;
}
__device__ __forceinline__ unsigned long long add2(unsigned long long a, unsigned long long b) {
    unsigned long long d;
    asm("add.rn.f32x2 %0, %1, %2;" : "=l"(d) : "l"(a), "l"(b));
    return d;
}
__device__ __forceinline__ unsigned long long pk2(float lo, float hi) {
    unsigned long long r;
    asm("mov.b64 %0, {%1, %2};" : "=l"(r) : "f"(lo), "f"(hi));
    return r;
}
__device__ __forceinline__ void upk2(float& lo, float& hi, unsigned long long v) {
    asm("mov.b64 {%0, %1}, %2;" : "=f"(lo), "=f"(hi) : "l"(v));
}

// ---------------- pack: Wcat/bcat (k|v|q|b|m), fused LSTM bias, barrier reset ----------------
__global__ void pack_kernel(const float* __restrict__ Wk, const float* __restrict__ bk,
                            const float* __restrict__ Wv, const float* __restrict__ bv,
                            const float* __restrict__ Wb, const float* __restrict__ bb,
                            const float* __restrict__ Wq, const float* __restrict__ bq,
                            const float* __restrict__ Wm, const float* __restrict__ bm,
                            const float* __restrict__ b_ih, const float* __restrict__ b_hh)
{
    int idx = blockIdx.x * 256 + threadIdx.x;
    if (idx == 0) g_bar_count = 0;      // reset monotonic grid-barrier counter every launch/replay
    if (idx < NP * HS) {
        int row = idx / HS, col = idx % HS;
        float v;
        if      (row < 64)  v = Wk[row * HS + col];
        else if (row < 128) v = Wv[(row - 64) * HS + col];
        else if (row < 192) v = Wq[(row - 128) * HS + col];
        else if (row == 192) v = Wb[col];
        else                 v = Wm[col];
        g_Wcat[idx] = v;
    } else if (idx < NP * HS + NP) {
        int row = idx - NP * HS;
        float v;
        if      (row < 64)  v = bk[row];
        else if (row < 128) v = bv[row - 64];
        else if (row < 192) v = bq[row - 128];
        else if (row == 192) v = bb[0];
        else                 v = bm[0];
        g_bcat[row] = v;
    } else if (idx < NP * HS + NP + G4) {
        int r = idx - NP * HS - NP;
        g_blstm[r] = b_ih[r] + b_hh[r];
    }
}

// ---------------- SGEMM: C[M,N] = A[M,K] @ B[N,K]^T + bias[N] ----------------
__global__ void __launch_bounds__(256)
sgemm_bias(const float* __restrict__ A, int lda,
           const float* __restrict__ B, int ldb,
           const float* __restrict__ bias,
           float* __restrict__ C, int ldc,
           int N, int K)
{
    __shared__ __align__(16) float As[2][16][132];
    __shared__ __align__(16) float Bs[2][16][132];
    const int tid = threadIdx.x;
    const int m0 = blockIdx.y * 128, n0 = blockIdx.x * 128;
    const int lrow = tid >> 1;
    const int lcol = (tid & 1) * 8;
    const int tx = tid & 15, ty = tid >> 4;
    const int tn0 = tx * 8, tm0 = ty * 8;

    unsigned long long acc2[4][8];
#pragma unroll
    for (int i = 0; i < 4; i++)
#pragma unroll
        for (int j = 0; j < 8; j++) acc2[i][j] = 0ull;

    const float* Arow = A + (size_t)(m0 + lrow) * lda;
    const bool  bok   = (n0 + lrow) < N;
    const float* Brow = B + (size_t)(bok ? (n0 + lrow) : 0) * ldb;

    float4 a0, a1, b0, b1;
    a0 = *reinterpret_cast<const float4*>(Arow + lcol);
    a1 = *reinterpret_cast<const float4*>(Arow + lcol + 4);
    b0 = b1 = make_float4(0.f, 0.f, 0.f, 0.f);
    if (bok) {
        b0 = *reinterpret_cast<const float4*>(Brow + lcol);
        b1 = *reinterpret_cast<const float4*>(Brow + lcol + 4);
    }
    int buf = 0;
    {
        As[0][lcol + 0][lrow] = a0.x; As[0][lcol + 1][lrow] = a0.y;
        As[0][lcol + 2][lrow] = a0.z; As[0][lcol + 3][lrow] = a0.w;
        As[0][lcol + 4][lrow] = a1.x; As[0][lcol + 5][lrow] = a1.y;
        As[0][lcol + 6][lrow] = a1.z; As[0][lcol + 7][lrow] = a1.w;
        Bs[0][lcol + 0][lrow] = b0.x; Bs[0][lcol + 1][lrow] = b0.y;
        Bs[0][lcol + 2][lrow] = b0.z; Bs[0][lcol + 3][lrow] = b0.w;
        Bs[0][lcol + 4][lrow] = b1.x; Bs[0][lcol + 5][lrow] = b1.y;
        Bs[0][lcol + 6][lrow] = b1.z; Bs[0][lcol + 7][lrow] = b1.w;
    }
    __syncthreads();

    for (int k0 = 0; k0 < K; k0 += 16) {
        const bool more = (k0 + 16) < K;
        if (more) {
            a0 = *reinterpret_cast<const float4*>(Arow + k0 + 16 + lcol);
            a1 = *reinterpret_cast<const float4*>(Arow + k0 + 16 + lcol + 4);
            if (bok) {
                b0 = *reinterpret_cast<const float4*>(Brow + k0 + 16 + lcol);
                b1 = *reinterpret_cast<const float4*>(Brow + k0 + 16 + lcol + 4);
            }
        }
#pragma unroll
        for (int k = 0; k < 16; k++) {
            const ulonglong2* Ap = reinterpret_cast<const ulonglong2*>(&As[buf][k][tm0]);
            ulonglong2 A01 = Ap[0], A23 = Ap[1];
            float4 bl = *reinterpret_cast<const float4*>(&Bs[buf][k][tn0]);
            float4 bh = *reinterpret_cast<const float4*>(&Bs[buf][k][tn0 + 4]);
            unsigned long long ap[4] = {A01.x, A01.y, A23.x, A23.y};
            unsigned long long bd[8] = {pk2(bl.x, bl.x), pk2(bl.y, bl.y),
                                        pk2(bl.z, bl.z), pk2(bl.w, bl.w),
                                        pk2(bh.x, bh.x), pk2(bh.y, bh.y),
                                        pk2(bh.z, bh.z), pk2(bh.w, bh.w)};
#pragma unroll
            for (int i = 0; i < 4; i++)
#pragma unroll
                for (int j = 0; j < 8; j++)
                    acc2[i][j] = ffma2(ap[i], bd[j], acc2[i][j]);
        }
        if (more) {
            int nb = buf ^ 1;
            As[nb][lcol + 0][lrow] = a0.x; As[nb][lcol + 1][lrow] = a0.y;
            As[nb][lcol + 2][lrow] = a0.z; As[nb][lcol + 3][lrow] = a0.w;
            As[nb][lcol + 4][lrow] = a1.x; As[nb][lcol + 5][lrow] = a1.y;
            As[nb][lcol + 6][lrow] = a1.z; As[nb][lcol + 7][lrow] = a1.w;
            Bs[nb][lcol + 0][lrow] = b0.x; Bs[nb][lcol + 1][lrow] = b0.y;
            Bs[nb][lcol + 2][lrow] = b0.z; Bs[nb][lcol + 3][lrow] = b0.w;
            Bs[nb][lcol + 4][lrow] = b1.x; Bs[nb][lcol + 5][lrow] = b1.y;
            Bs[nb][lcol + 6][lrow] = b1.z; Bs[nb][lcol + 7][lrow] = b1.w;
            __syncthreads();
            buf = nb;
        }
    }

    const bool vec = ((ldc & 3) == 0) && (n0 + tn0 + 7) < N;
#pragma unroll
    for (int i = 0; i < 4; i++) {
        float lo[8], hi[8];
#pragma unroll
        for (int j = 0; j < 8; j++) upk2(lo[j], hi[j], acc2[i][j]);
        size_t r0 = (size_t)(m0 + tm0 + 2 * i) * ldc + n0 + tn0;
        size_t r1 = r0 + ldc;
        if (vec) {
            float4 bl = *reinterpret_cast<const float4*>(bias + n0 + tn0);
            float4 bh = *reinterpret_cast<const float4*>(bias + n0 + tn0 + 4);
            *reinterpret_cast<float4*>(C + r0)     = make_float4(lo[0] + bl.x, lo[1] + bl.y, lo[2] + bl.z, lo[3] + bl.w);
            *reinterpret_cast<float4*>(C + r0 + 4) = make_float4(lo[4] + bh.x, lo[5] + bh.y, lo[6] + bh.z, lo[7] + bh.w);
            *reinterpret_cast<float4*>(C + r1)     = make_float4(hi[0] + bl.x, hi[1] + bl.y, hi[2] + bl.z, hi[3] + bl.w);
            *reinterpret_cast<float4*>(C + r1 + 4) = make_float4(hi[4] + bh.x, hi[5] + bh.y, hi[6] + bh.z, hi[7] + bh.w);
        } else {
#pragma unroll
            for (int j = 0; j < 8; j++) {
                int n = n0 + tn0 + j;
                if (n < N) {
                    float bv_ = bias[n];
                    C[r0 + j] = lo[j] + bv_;
                    C[r1 + j] = hi[j] + bv_;
                }
            }
        }
    }
}

// ---------------- xproj-transposed SGEMM ----------------
// C_T[(n>>5)*G4*32 + m*32 + (n&31)] = sum_k A[m,k]*B[n,k] + bias[m]
__global__ void __launch_bounds__(256)
sgemm_bias_xT(const float* __restrict__ A, const float* __restrict__ B,
              const float* __restrict__ bias, float* __restrict__ C, int K)
{
    __shared__ __align__(16) float As[2][16][132];
    __shared__ __align__(16) float Bs[2][16][132];
    const int tid = threadIdx.x;
    const int m0 = blockIdx.y * 128, n0 = blockIdx.x * 128;
    const int lrow = tid >> 1;
    const int lcol = (tid & 1) * 8;
    const int tx = tid & 15, ty = tid >> 4;
    const int tn0 = tx * 8, tm0 = ty * 8;

    unsigned long long acc2[4][8];
#pragma unroll
    for (int i = 0; i < 4; i++)
#pragma unroll
        for (int j = 0; j < 8; j++) acc2[i][j] = 0ull;

    const float* Arow = A + (size_t)(m0 + lrow) * ISZ;
    const float* Brow = B + (size_t)(n0 + lrow) * ISZ;

    float4 a0, a1, b0, b1;
    a0 = *reinterpret_cast<const float4*>(Arow + lcol);
    a1 = *reinterpret_cast<const float4*>(Arow + lcol + 4);
    b0 = *reinterpret_cast<const float4*>(Brow + lcol);
    b1 = *reinterpret_cast<const float4*>(Brow + lcol + 4);
    int buf = 0;
    {
        As[0][lcol + 0][lrow] = a0.x; As[0][lcol + 1][lrow] = a0.y;
        As[0][lcol + 2][lrow] = a0.z; As[0][lcol + 3][lrow] = a0.w;
        As[0][lcol + 4][lrow] = a1.x; As[0][lcol + 5][lrow] = a1.y;
        As[0][lcol + 6][lrow] = a1.z; As[0][lcol + 7][lrow] = a1.w;
        Bs[0][lcol + 0][lrow] = b0.x; Bs[0][lcol + 1][lrow] = b0.y;
        Bs[0][lcol + 2][lrow] = b0.z; Bs[0][lcol + 3][lrow] = b0.w;
        Bs[0][lcol + 4][lrow] = b1.x; Bs[0][lcol + 5][lrow] = b1.y;
        Bs[0][lcol + 6][lrow] = b1.z; Bs[0][lcol + 7][lrow] = b1.w;
    }
    __syncthreads();

    for (int k0 = 0; k0 < K; k0 += 16) {
        const bool more = (k0 + 16) < K;
        if (more) {
            a0 = *reinterpret_cast<const float4*>(Arow + k0 + 16 + lcol);
            a1 = *reinterpret_cast<const float4*>(Arow + k0 + 16 + lcol + 4);
            b0 = *reinterpret_cast<const float4*>(Brow + k0 + 16 + lcol);
            b1 = *reinterpret_cast<const float4*>(Brow + k0 + 16 + lcol + 4);
        }
#pragma unroll
        for (int k = 0; k < 16; k++) {
            const ulonglong2* Ap = reinterpret_cast<const ulonglong2*>(&As[buf][k][tm0]);
            ulonglong2 A01 = Ap[0], A23 = Ap[1];
            float4 bl = *reinterpret_cast<const float4*>(&Bs[buf][k][tn0]);
            float4 bh = *reinterpret_cast<const float4*>(&Bs[buf][k][tn0 + 4]);
            unsigned long long ap[4] = {A01.x, A01.y, A23.x, A23.y};
            unsigned long long bd[8] = {pk2(bl.x, bl.x), pk2(bl.y, bl.y),
                                        pk2(bl.z, bl.z), pk2(bl.w, bl.w),
                                        pk2(bh.x, bh.x), pk2(bh.y, bh.y),
                                        pk2(bh.z, bh.z), pk2(bh.w, bh.w)};
#pragma unroll
            for (int i = 0; i < 4; i++)
#pragma unroll
                for (int j = 0; j < 8; j++)
                    acc2[i][j] = ffma2(ap[i], bd[j], acc2[i][j]);
        }
        if (more) {
            int nb = buf ^ 1;
            As[nb][lcol + 0][lrow] = a0.x; As[nb][lcol + 1][lrow] = a0.y;
            As[nb][lcol + 2][lrow] = a0.z; As[nb][lcol + 3][lrow] = a0.w;
            As[nb][lcol + 4][lrow] = a1.x; As[nb][lcol + 5][lrow] = a1.y;
            As[nb][lcol + 6][lrow] = a1.z; As[nb][lcol + 7][lrow] = a1.w;
            Bs[nb][lcol + 0][lrow] = b0.x; Bs[nb][lcol + 1][lrow] = b0.y;
            Bs[nb][lcol + 2][lrow] = b0.z; Bs[nb][lcol + 3][lrow] = b0.w;
            Bs[nb][lcol + 4][lrow] = b1.x; Bs[nb][lcol + 5][lrow] = b1.y;
            Bs[nb][lcol + 6][lrow] = b1.z; Bs[nb][lcol + 7][lrow] = b1.w;
            __syncthreads();
            buf = nb;
        }
    }

    const int nb_ = n0 + tn0;
    const size_t grp = (size_t)(nb_ >> 5) * G4 * 32 + (nb_ & 31);
#pragma unroll
    for (int i = 0; i < 4; i++) {
        float lo[8], hi[8];
#pragma unroll
        for (int j = 0; j < 8; j++) upk2(lo[j], hi[j], acc2[i][j]);
        int mlo = m0 + tm0 + 2 * i, mhi = mlo + 1;
        float blo = bias[mlo], bhi = bias[mhi];
        float* plo = C + grp + (size_t)mlo * 32;
        float* phi = C + grp + (size_t)mhi * 32;
        *reinterpret_cast<float4*>(plo)     = make_float4(lo[0] + blo, lo[1] + blo, lo[2] + blo, lo[3] + blo);
        *reinterpret_cast<float4*>(plo + 4) = make_float4(lo[4] + blo, lo[5] + blo, lo[6] + blo, lo[7] + blo);
        *reinterpret_cast<float4*>(phi)     = make_float4(hi[0] + bhi, hi[1] + bhi, hi[2] + bhi, hi[3] + bhi);
        *reinterpret_cast<float4*>(phi + 4) = make_float4(hi[4] + bhi, hi[5] + bhi, hi[6] + bhi, hi[7] + bhi);
    }
}

// ---------------- persistent LSTM scan (512 thr/block, FFMA2) ----------------
__device__ __forceinline__ void grid_barrier(unsigned target)
{
    __syncthreads();
    if (threadIdx.x == 0) {
        unsigned* p = &g_bar_count;
        asm volatile("red.release.gpu.global.add.u32 [%0], 1;" :: "l"(p) : "memory");
        unsigned v;
        do {
            asm volatile("ld.acquire.gpu.global.u32 %0, [%1];" : "=r"(v) : "l"(p) : "memory");
        } while ((int)(v - target) < 0);
    }
    __syncthreads();
}

// dynamic smem layout (bytes):
//   [0, 32768)           float4 Wq[256][8]
//   [32768, 65536)       u64 red2[16][8][32]
//   [65536, 67584)       float gates[16][32]
//   [67584, 68096)       float c_s[4][32]
#define LSMEM_BYTES 68096

__global__ void __launch_bounds__(512)
lstm_kernel(const float* __restrict__ h0, const float* __restrict__ c0,
            const float* __restrict__ W_hh, float* __restrict__ out)
{
    extern __shared__ __align__(16) char smem[];
    float4*              Wq     = reinterpret_cast<float4*>(smem);
    unsigned long long*  red2   = reinterpret_cast<unsigned long long*>(smem + 32768);
    float*               gates  = reinterpret_cast<float*>(smem + 65536);
    float*               c_s    = reinterpret_cast<float*>(smem + 67584);

    const int bid = blockIdx.x, tid = threadIdx.x;
    const int w = tid >> 5, lane = tid & 31;

    // stage W_hh pairs: Wq[jh][rp]
    for (int idx = tid; idx < 256 * 8; idx += 512) {
        int jh = idx >> 3, rp = idx & 7;
        int r0 = 2 * rp, r1 = 2 * rp + 1;
        size_t g0 = (size_t)((r0 >> 2) * HS + bid * 4 + (r0 & 3)) * HS;
        size_t g1 = (size_t)((r1 >> 2) * HS + bid * 4 + (r1 & 3)) * HS;
        int j0 = 2 * jh, j1 = 2 * jh + 1;
        Wq[idx] = make_float4(W_hh[g0 + j0], W_hh[g1 + j0], W_hh[g0 + j1], W_hh[g1 + j1]);
    }
    if (tid < 128) {
        int c = tid & 3, b = tid >> 2;
        int jcol = bid * 4 + c;
        c_s[c * 32 + b] = c0[b * HS + jcol];
        ((float*)g_h4)[(bid * BB + b) * 4 + c] = h0[b * HS + jcol];  // buffer 0
    }

    // reduce-phase ownership: tid<256 -> row pair (2*rp8, 2*rp8+1) for batch bq
    const int rp8 = tid >> 5, bq = tid & 31;          // rp8 valid 0..7 for tid<256
    const int r0x = 2 * (rp8 & 7);
    const size_t grow0 = (size_t)((r0x >> 2) * HS + bid * 4 + (r0x & 3));
    const float* xpp = g_xproj + grow0 * 32 + bq;     // row r0x; row r0x+1 at +32 floats
    float xp0 = 0.f, xp1 = 0.f;
    if (tid < 256) { xp0 = xpp[0]; xp1 = xpp[32]; }

    // gate-phase ownership
    const int cc = tid & 3, ba = tid >> 2;
    const int jcol = bid * 4 + cc;

    unsigned barn = 1;
    grid_barrier(barn * NLB);

    for (int t = 0; t < TS; t++) {
        const float4* hbuf = g_h4 + (size_t)(t & 1) * (HS / 4) * BB;
        float*        hout = (float*)(g_h4 + (size_t)((t + 1) & 1) * (HS / 4) * BB);

        // front-load all h for this warp's K-slice (MLP=8, single exposed latency)
        float4 hv[8];
#pragma unroll
        for (int jq = 0; jq < 8; jq++)
            hv[jq] = hbuf[(w * 8 + jq) * BB + lane];

        // prefetch next step's x_proj pair (independent of h) — hidden under FMA2 phase
        float xp0n = 0.f, xp1n = 0.f;
        if (tid < 256 && t + 1 < TS) {
            const float* xn = xpp + (size_t)(t + 1) * G4 * 32;
            xp0n = xn[0]; xp1n = xn[32];
        }

        unsigned long long acc2[8];
#pragma unroll
        for (int rp = 0; rp < 8; rp++) acc2[rp] = 0ull;

#pragma unroll
        for (int jq = 0; jq < 8; jq++) {
            unsigned long long p0 = pk2(hv[jq].x, hv[jq].x);
            unsigned long long p1 = pk2(hv[jq].y, hv[jq].y);
            unsigned long long p2 = pk2(hv[jq].z, hv[jq].z);
            unsigned long long p3 = pk2(hv[jq].w, hv[jq].w);
            const ulonglong2* Wv = reinterpret_cast<const ulonglong2*>(Wq + ((w * 16 + jq * 2) * 8));
#pragma unroll
            for (int rp = 0; rp < 8; rp++) {
                ulonglong2 w0 = Wv[rp];
                ulonglong2 w1 = Wv[8 + rp];
                acc2[rp] = ffma2(p0, w0.x, acc2[rp]);
                acc2[rp] = ffma2(p1, w0.y, acc2[rp]);
                acc2[rp] = ffma2(p2, w1.x, acc2[rp]);
                acc2[rp] = ffma2(p3, w1.y, acc2[rp]);
            }
        }
#pragma unroll
        for (int rp = 0; rp < 8; rp++)
            red2[(w * 8 + rp) * 32 + lane] = acc2[rp];
        __syncthreads();

        // paired reduce: 256 threads, u64 adds (both rows of the pair at once)
        if (tid < 256) {
            unsigned long long s2 = pk2(xp0, xp1);
#pragma unroll
            for (int ww = 0; ww < 16; ww++)
                s2 = add2(s2, red2[(ww * 8 + rp8) * 32 + bq]);
            float lo, hi;
            upk2(lo, hi, s2);
            gates[(2 * rp8) * 32 + bq]     = lo;
            gates[(2 * rp8 + 1) * 32 + bq] = hi;
        }
        __syncthreads();

        float hn = 0.f;
        const bool wr = tid < 128;
        if (wr) {
            float gi = gates[(0 + cc) * 32 + ba];
            float gf = gates[(4 + cc) * 32 + ba];
            float gg = gates[(8 + cc) * 32 + ba];
            float go = gates[(12 + cc) * 32 + ba];
            float cn = sigm_fast(gf) * c_s[cc * 32 + ba] + sigm_fast(gi) * tanh_fast(gg);
            hn = sigm_fast(go) * tanh_fast(cn);
            c_s[cc * 32 + ba] = cn;
            hout[(bid * BB + ba) * 4 + cc] = hn;
        }
        xp0 = xp0n; xp1 = xp1n;
        ++barn;
        grid_barrier(barn * NLB);
        // h_seq store is only consumed after this kernel ends — issue it off the
        // critical path (overlaps the next step's loads/FMA phase)
        if (wr) out[((size_t)t * BB + ba) * (2 * HS) + jcol] = hn;
    }
}

// ---------------- elu/normalize/sigmoid over packed projections ----------------
__global__ void __launch_bounds__(256) postproc_kernel()
{
    const int w = threadIdx.x >> 5, lane = threadIdx.x & 31;
    const int tb = blockIdx.x * 8 + w;
    const float* rp = g_raw + (size_t)tb * NP;

    float a0 = elup1(rp[lane]), a1 = elup1(rp[32 + lane]);
    float s = a0 + a1;
#pragma unroll
    for (int off = 16; off > 0; off >>= 1) s += __shfl_xor_sync(0xffffffffu, s, off);
    float inv = 1.f / s;
    g_ks[(size_t)tb * KS + lane]      = a0 * inv;
    g_ks[(size_t)tb * KS + 32 + lane] = a1 * inv;

    g_vs[(size_t)tb * VS + lane]      = rp[64 + lane];
    g_vs[(size_t)tb * VS + 32 + lane] = rp[96 + lane];

    float q0 = elup1(rp[128 + lane]), q1 = elup1(rp[160 + lane]);
    float sq = q0 + q1;
#pragma unroll
    for (int off = 16; off > 0; off >>= 1) sq += __shfl_xor_sync(0xffffffffu, sq, off);
    float invq = 1.f / sq;
    g_qs[(size_t)tb * KS + lane]      = q0 * invq;
    g_qs[(size_t)tb * KS + 32 + lane] = q1 * invq;

    if (lane == 0) {
        g_bs[tb] = sigm(rp[192]);
        g_ms[tb] = sigm(rp[193]);
    }
}

// ---------------- delta-rule scan: 64 blocks (b x v-half), 128 thr, 4-way k-split ----------------
__global__ void __launch_bounds__(128) fwm_kernel(const float* __restrict__ F0)
{
    const int b  = blockIdx.x >> 1;
    const int vh = (blockIdx.x & 1) * 32;
    const int tid = threadIdx.x;
    const int vl = tid >> 2;
    const int kq = tid & 3, kb = kq * 16;
    const int v = vh + vl;

    float F[16];
#pragma unroll
    for (int k = 0; k < 16; k++) F[k] = F0[((size_t)b * VS + v) * KS + kb + k];

    __shared__ float k_s[64], q_s[64];

    const float* srcp = (tid < 64) ? (g_ks + tid) : (g_qs + (tid - 64));
    float* dstp = (tid < 64) ? (k_s + tid) : (q_s + (tid - 64));

    size_t base0 = (size_t)b * KS;
    float ld1 = srcp[base0];
    float pv  = g_vs[base0 + v];
    float pb  = g_bs[b];
    float pm  = g_ms[b];

    for (int t = 0; t < TS; t++) {
        *dstp = ld1;
        float vt = pv, bc = pb, mc = pm;
        __syncthreads();

        if (t + 1 < TS) {
            size_t base1 = ((size_t)(t + 1) * BB + b) * KS;
            ld1 = srcp[base1];
            pv  = g_vs[base1 + v];
            pb  = g_bs[(t + 1) * BB + b];
            pm  = g_ms[(t + 1) * BB + b];
        }

        float d0 = 0.f, d1 = 0.f, d2 = 0.f, d3 = 0.f;
#pragma unroll
        for (int k = 0; k < 16; k += 4) {
            d0 = fmaf(F[k],     k_s[kb + k],     d0);
            d1 = fmaf(F[k + 1], k_s[kb + k + 1], d1);
            d2 = fmaf(F[k + 2], k_s[kb + k + 2], d2);
            d3 = fmaf(F[k + 3], k_s[kb + k + 3], d3);
        }
        float d = (d0 + d1) + (d2 + d3);
        d += __shfl_xor_sync(0xffffffffu, d, 1);
        d += __shfl_xor_sync(0xffffffffu, d, 2);
        float nv = bc * (vt - d);

        float o0 = 0.f, o1 = 0.f, o2 = 0.f, o3 = 0.f;
#pragma unroll
        for (int k = 0; k < 16; k += 4) {
            F[k]     = fmaf(nv, k_s[kb + k],     F[k]);     o0 = fmaf(F[k],     q_s[kb + k],     o0);
            F[k + 1] = fmaf(nv, k_s[kb + k + 1], F[k + 1]); o1 = fmaf(F[k + 1], q_s[kb + k + 1], o1);
            F[k + 2] = fmaf(nv, k_s[kb + k + 2], F[k + 2]); o2 = fmaf(F[k + 2], q_s[kb + k + 2], o2);
            F[k + 3] = fmaf(nv, k_s[kb + k + 3], F[k + 3]); o3 = fmaf(F[k + 3], q_s[kb + k + 3], o3);
        }
        float o = (o0 + o1) + (o2 + o3);
        o += __shfl_xor_sync(0xffffffffu, o, 1);
        o += __shfl_xor_sync(0xffffffffu, o, 2);
        if (kq == 0)
            g_s[((size_t)t * BB + b) * VS + v] = o * mc;
        __syncthreads();
    }
}

// ---------------- launch ----------------
extern "C" void kernel_launch(void* const* d_in, const int* in_sizes, int n_in,
                              void* d_out, int out_size)
{
    const float* inputs = (const float*)d_in[0];
    const float* h0     = (const float*)d_in[1];
    const float* c0     = (const float*)d_in[2];
    const float* F0     = (const float*)d_in[3];
    const float* W_ih   = (const float*)d_in[4];
    const float* W_hh   = (const float*)d_in[5];
    const float* b_ih   = (const float*)d_in[6];
    const float* b_hh   = (const float*)d_in[7];
    const float* Wk = (const float*)d_in[8],  *bk = (const float*)d_in[9];
    const float* Wv = (const float*)d_in[10], *bv = (const float*)d_in[11];
    const float* Wb = (const float*)d_in[12], *bb = (const float*)d_in[13];
    const float* Wq = (const float*)d_in[14], *bq = (const float*)d_in[15];
    const float* Wm = (const float*)d_in[16], *bm = (const float*)d_in[17];
    const float* Wlin = (const float*)d_in[18], *blin = (const float*)d_in[19];
    float* out = (float*)d_out;

    float *p_xproj, *p_raw, *p_s, *p_Wcat, *p_bcat, *p_blstm;
    cudaGetSymbolAddress((void**)&p_xproj, g_xproj);
    cudaGetSymbolAddress((void**)&p_raw,   g_raw);
    cudaGetSymbolAddress((void**)&p_s,     g_s);
    cudaGetSymbolAddress((void**)&p_Wcat,  g_Wcat);
    cudaGetSymbolAddress((void**)&p_bcat,  g_bcat);
    cudaGetSymbolAddress((void**)&p_blstm, g_blstm);

    static int smem_set = 0;
    if (!smem_set) {
        cudaFuncSetAttribute(lstm_kernel, cudaFuncAttributeMaxDynamicSharedMemorySize, LSMEM_BYTES);
        smem_set = 1;
    }

    // 1. pack weights/biases (+ barrier counter reset)
    pack_kernel<<<(NP * HS + NP + G4 + 255) / 256, 256>>>(Wk, bk, Wv, bv, Wb, bb, Wq, bq, Wm, bm, b_ih, b_hh);
    // 2. xprojT[t][gate][b] = W_ih @ inputs^T + blstm (transposed store, coalesced LSTM reads)
    sgemm_bias_xT<<<dim3((TS * BB) / 128, G4 / 128), 256>>>(W_ih, inputs, p_blstm, p_xproj, ISZ);
    // 3. sequential LSTM (writes h into out[:, :512] and h double-buffer)
    lstm_kernel<<<NLB, 512, LSMEM_BYTES>>>(h0, c0, W_hh, out);
    // 4. packed FWM projections: raw = h_seq @ Wcat^T + bcat   [65536 x 194]
    sgemm_bias<<<dim3((NP + 127) / 128, (TS * BB) / 128), 256>>>(out, 2 * HS, p_Wcat, HS, p_bcat, p_raw, NP, NP, HS);
    // 5. elu+1 normalize / sigmoid
    postproc_kernel<<<(TS * BB) / 8, 256>>>();
    // 6. sequential fast-weight scan (b x v-half split)
    fwm_kernel<<<2 * BB, 128>>>(F0);
    // 7. out[:, 512:] = s @ Wlin^T + blin
    sgemm_bias<<<dim3(HS / 128, (TS * BB) / 128), 256>>>(p_s, VS, Wlin, VS, blin, out + HS, 2 * HS, HS, VS);
}